// round 15
// baseline (speedup 1.0000x reference)
#include <cuda_runtime.h>
#include <cstdint>

#define N_NODES 50000
#define N_EDGES 800000
#define D 64
#define DH 8
#define NSEG (N_NODES * DH)

#define TM 128
#define GRID_X ((N_NODES + TM - 1) / TM)   // 391

// smem: sA = 128 rows x 72 (hi,lo) uint2 slots; sB = 64 n-rows x 72
#define SA_STRIDE 72
#define SB_STRIDE 72
#define SB_OFF (128 * SA_STRIDE)                 // uint2 index
#define SMEM_MMA_BYTES ((128 * SA_STRIDE + 64 * SB_STRIDE) * 8)   // 110592

// k-slot permutation within each 8-k block: thread t's k=t and k=t+4 land in
// adjacent slots 2t, 2t+1 (one LDS.128 fetches hi/lo of both).
#define SLOT(k) (((k) & ~7) + (((k) & 3) << 1) + (((k) >> 2) & 1))

typedef unsigned long long u64;

// Device scratch (no cudaMalloc allowed)
__device__ __align__(16) float g_q[N_NODES * D];
__device__ __align__(16) float g_k[N_NODES * D];
__device__ __align__(16) float g_s[NSEG];

// ---- tf32 helpers ----
__device__ __forceinline__ uint32_t f2tf32(float f) {
    uint32_t r;
    asm("cvt.rna.tf32.f32 %0, %1;" : "=r"(r) : "f"(f));
    return r;
}
__device__ __forceinline__ uint2 tfpair(float f) {
    uint32_t hi = f2tf32(f);
    float rem = f - __uint_as_float(hi);
    uint32_t lo = f2tf32(rem);
    return make_uint2(hi, lo);
}

__device__ __forceinline__ void mma_tf32(float c[4],
                                         uint32_t a0, uint32_t a1, uint32_t a2, uint32_t a3,
                                         uint32_t b0, uint32_t b1) {
    asm volatile(
        "mma.sync.aligned.m16n8k8.row.col.f32.tf32.tf32.f32 "
        "{%0,%1,%2,%3}, {%4,%5,%6,%7}, {%8,%9}, {%0,%1,%2,%3};"
        : "+f"(c[0]), "+f"(c[1]), "+f"(c[2]), "+f"(c[3])
        : "r"(a0), "r"(a1), "r"(a2), "r"(a3), "r"(b0), "r"(b1));
}

// ---------------------------------------------------------------------------
// Tensor-core QKV GEMM via mma.sync tf32 (3xTF32 split, fp32 accum).
// Grid (391, 3): blockIdx.y selects {Wq,Wk,Wv}; 256 threads; warp = 16x64.
// tf32 m16n8k8 fragment map (CUTLASS SM80_16x8x8_F32TF32TF32F32_TN):
//   A: a0=(g,t) a1=(g+8,t) a2=(g,t+4) a3=(g+8,t+4)
//   B: b0=(k=t,n=g) b1=(k=t+4,n=g)
//   C: c0,c1=(g,2t),(g,2t+1)  c2,c3=(g+8,2t),(g+8,2t+1)
// ---------------------------------------------------------------------------
__global__ __launch_bounds__(256) void qkv_mma_kernel(
    const float* __restrict__ x,
    const float* __restrict__ Wq, const float* __restrict__ bq,
    const float* __restrict__ Wk, const float* __restrict__ bk,
    const float* __restrict__ Wv, const float* __restrict__ bv,
    float* __restrict__ vout)
{
    extern __shared__ __align__(16) uint2 smp[];
    uint2* sA = smp;            // idx = row*SA_STRIDE + SLOT(k)
    uint2* sB = smp + SB_OFF;   // idx = n*SB_STRIDE + SLOT(k)

    const int tid = threadIdx.x;
    const int mat = blockIdx.y;
    const int n0 = blockIdx.x * TM;

    const float* W    = (mat == 0) ? Wq : (mat == 1) ? Wk : Wv;
    const float* bias = (mat == 0) ? bq : (mat == 1) ? bk : bv;
    float* dst        = (mat == 0) ? g_q : (mat == 1) ? g_k : vout;

    // Fused init: zero g_s (100000 float4; 391*256 = 100096 threads in y==0)
    if (mat == 0) {
        int g = blockIdx.x * 256 + tid;
        if (g < NSEG / 4) ((float4*)g_s)[g] = make_float4(0.f, 0.f, 0.f, 0.f);
    }

    // Load x tile: 128 rows x 64 cols fp32 -> tf32 (hi,lo) pairs, k-permuted
    {
        const float4* x4 = (const float4*)x;
#pragma unroll
        for (int i = tid; i < 2048; i += 256) {
            int row = i >> 4;
            int c4  = (i & 15) * 4;
            int gn  = n0 + row;
            float4 v = (gn < N_NODES) ? x4[(size_t)gn * 16 + (i & 15)]
                                      : make_float4(0.f, 0.f, 0.f, 0.f);
            uint2* a = &sA[row * SA_STRIDE];
            a[SLOT(c4 + 0)] = tfpair(v.x);
            a[SLOT(c4 + 1)] = tfpair(v.y);
            a[SLOT(c4 + 2)] = tfpair(v.z);
            a[SLOT(c4 + 3)] = tfpair(v.w);
        }
    }
    // Load W: fp32 [k][n] row-major -> sB[n][SLOT(k)] pairs (transposed)
    {
        const float4* W4 = (const float4*)W;
#pragma unroll
        for (int i = tid; i < 1024; i += 256) {
            int k  = i >> 4;
            int c4 = (i & 15) * 4;
            float4 w = W4[i];
            int ks = SLOT(k);
            sB[(c4 + 0) * SB_STRIDE + ks] = tfpair(w.x);
            sB[(c4 + 1) * SB_STRIDE + ks] = tfpair(w.y);
            sB[(c4 + 2) * SB_STRIDE + ks] = tfpair(w.z);
            sB[(c4 + 3) * SB_STRIDE + ks] = tfpair(w.w);
        }
    }
    __syncthreads();

    const int wid  = tid >> 5;
    const int lane = tid & 31;
    const int g    = lane >> 2;     // groupID
    const int t    = lane & 3;      // threadID_in_group
    const int mrow = wid * 16;      // warp's 16-row slab

    float acc[8][4];
#pragma unroll
    for (int n = 0; n < 8; n++)
#pragma unroll
        for (int j = 0; j < 4; j++) acc[n][j] = 0.f;

#pragma unroll
    for (int kk = 0; kk < 8; kk++) {
        const int ks = kk * 8 + 2 * t;   // slots 2t, 2t+1 = k=t, k=t+4
        // {hi(k=t), lo(k=t), hi(k=t+4), lo(k=t+4)} per row
        uint4 Ar0 = *(const uint4*)&sA[(mrow + g) * SA_STRIDE + ks];
        uint4 Ar8 = *(const uint4*)&sA[(mrow + g + 8) * SA_STRIDE + ks];
        // a = {(g,t), (g+8,t), (g,t+4), (g+8,t+4)}
        uint32_t ah0 = Ar0.x, ah1 = Ar8.x, ah2 = Ar0.z, ah3 = Ar8.z;
        uint32_t al0 = Ar0.y, al1 = Ar8.y, al2 = Ar0.w, al3 = Ar8.w;
#pragma unroll
        for (int n = 0; n < 8; n++) {
            uint4 Bv = *(const uint4*)&sB[(n * 8 + g) * SB_STRIDE + ks];
            uint32_t bh0 = Bv.x, bh1 = Bv.z;   // (k=t,n=g), (k=t+4,n=g)
            uint32_t bl0 = Bv.y, bl1 = Bv.w;
            mma_tf32(acc[n], ah0, ah1, ah2, ah3, bh0, bh1);
            mma_tf32(acc[n], ah0, ah1, ah2, ah3, bl0, bl1);
            mma_tf32(acc[n], al0, al1, al2, al3, bh0, bh1);
        }
    }

    // Epilogue: rows {g, g+8}, cols {2t, 2t+1} within each 8-col tile.
    const int row0 = n0 + mrow + g;
    const int row8 = row0 + 8;
#pragma unroll
    for (int n = 0; n < 8; n++) {
        int col = n * 8 + t * 2;
        float2 b2 = *(const float2*)&bias[col];
        if (row0 < N_NODES) {
            *(float2*)&dst[(size_t)row0 * 64 + col] =
                make_float2(acc[n][0] + b2.x, acc[n][1] + b2.y);
        }
        if (row8 < N_NODES) {
            *(float2*)&dst[(size_t)row8 * 64 + col] =
                make_float2(acc[n][2] + b2.x, acc[n][3] + b2.y);
        }
    }
}

// ---------------------------------------------------------------------------
// Warp-cooperative fused edge pass: logits + exp + vec4-atomic segment sum.
// 8 lanes per edge, 4 edges per warp; all gathers coalesced.
// ---------------------------------------------------------------------------
__global__ __launch_bounds__(256) void edge_fused_kernel(
    const int* __restrict__ edge, float* __restrict__ prods)
{
    const int lane = threadIdx.x & 31;
    const int warp = (blockIdx.x * 256 + threadIdx.x) >> 5;
    const int e0   = warp * 4;
    const int sub  = lane >> 3;
    const int d    = lane & 7;
    const int e    = e0 + sub;

    const int src = edge[e];
    const int dst = edge[N_EDGES + e];

    const float4* q4 = (const float4*)(g_q + src * D);
    const float4* k4 = (const float4*)(g_k + dst * D);

    float4 qa = q4[d];
    float4 qb = q4[d + 8];
    float4 ka = k4[d];
    float4 kb = k4[d + 8];

    float w0 = qa.x * ka.x + qb.x * kb.x;
    float w1 = qa.y * ka.y + qb.y * kb.y;
    float w2 = qa.z * ka.z + qb.z * kb.z;
    float w3 = qa.w * ka.w + qb.w * kb.w;

    const unsigned FULL = 0xffffffffu;

    {
        float t0 = (lane & 4) ? w0 : w2;
        float t1 = (lane & 4) ? w1 : w3;
        float u0 = __shfl_xor_sync(FULL, t0, 4);
        float u1 = __shfl_xor_sync(FULL, t1, 4);
        w0 = ((lane & 4) ? w2 : w0) + u0;
        w1 = ((lane & 4) ? w3 : w1) + u1;
    }
    float p;
    {
        float t2 = (lane & 2) ? w0 : w1;
        float u2 = __shfl_xor_sync(FULL, t2, 2);
        p = ((lane & 2) ? w1 : w0) + u2;
    }
    {
        int srcl = (sub << 3) | ((d >> 2) & 1) | ((d & 1) << 1) | ((d & 2) << 1);
        p = __shfl_sync(FULL, p, srcl);
    }

    p *= 0.35355339059327373f;  // 1/sqrt(8)

    size_t off = (size_t)e0 * 8 + lane;
    prods[off] = p;
    float ev = __expf(p);

    float p1 = __shfl_down_sync(FULL, ev, 1);
    float p2 = __shfl_down_sync(FULL, ev, 2);
    float p3 = __shfl_down_sync(FULL, ev, 3);
    if ((lane & 3) == 0) {
        float* srow = g_s + dst * 8 + (lane & 4);
        asm volatile("red.global.add.v4.f32 [%0], {%1, %2, %3, %4};"
                     :: "l"(srow), "f"(ev), "f"(p1), "f"(p2), "f"(p3) : "memory");
    }
}

// ---------------------------------------------------------------------------
// Pass C: att[e][d] = exp(prods[e][d]) / (s[dst][d] + 1e-16).
// ---------------------------------------------------------------------------
__global__ __launch_bounds__(256) void edge_scale_kernel(
    const int* __restrict__ edge, const float* __restrict__ prods,
    float* __restrict__ att)
{
    int e = blockIdx.x * blockDim.x + threadIdx.x;
    if (e >= N_EDGES) return;
    int dst = edge[N_EDGES + e];

    const float4* sr = (const float4*)(g_s + dst * 8);
    float4 s0 = sr[0];
    float4 s1 = sr[1];

    const float4* pr = (const float4*)(prods + (size_t)e * 8);
    float4 p0 = pr[0];
    float4 p1 = pr[1];

    float4 v0, v1;
    v0.x = __fdividef(__expf(p0.x), s0.x + 1e-16f);
    v0.y = __fdividef(__expf(p0.y), s0.y + 1e-16f);
    v0.z = __fdividef(__expf(p0.z), s0.z + 1e-16f);
    v0.w = __fdividef(__expf(p0.w), s0.w + 1e-16f);
    v1.x = __fdividef(__expf(p1.x), s1.x + 1e-16f);
    v1.y = __fdividef(__expf(p1.y), s1.y + 1e-16f);
    v1.z = __fdividef(__expf(p1.z), s1.z + 1e-16f);
    v1.w = __fdividef(__expf(p1.w), s1.w + 1e-16f);

    float4* ar = (float4*)(att + (size_t)e * 8);
    ar[0] = v0;
    ar[1] = v1;
}

// ---------------------------------------------------------------------------
// kernel_launch
// Inputs (metadata order): x, Wq, bq, Wk, bk, Wv, bv, edge
// Output: attention [E,8] | v [N,8,8] | prods [E,8]  (float32)
// ---------------------------------------------------------------------------
extern "C" void kernel_launch(void* const* d_in, const int* in_sizes, int n_in,
                              void* d_out, int out_size) {
    const float* x  = (const float*)d_in[0];
    const float* Wq = (const float*)d_in[1];
    const float* bq = (const float*)d_in[2];
    const float* Wk = (const float*)d_in[3];
    const float* bk = (const float*)d_in[4];
    const float* Wv = (const float*)d_in[5];
    const float* bv = (const float*)d_in[6];
    const int*   edge = (const int*)d_in[7];

    float* out   = (float*)d_out;
    float* att   = out;                          // E*8
    float* vout  = out + (size_t)N_EDGES * 8;    // N*64
    float* prods = vout + (size_t)N_NODES * 64;  // E*8

    static bool inited = false;
    if (!inited) {
        cudaFuncSetAttribute(qkv_mma_kernel,
                             cudaFuncAttributeMaxDynamicSharedMemorySize,
                             SMEM_MMA_BYTES);
        inited = true;
    }

    dim3 grid(GRID_X, 3);
    qkv_mma_kernel<<<grid, 256, SMEM_MMA_BYTES>>>(x, Wq, bq, Wk, bk, Wv, bv, vout);
    edge_fused_kernel<<<N_EDGES / 32, 256>>>(edge, prods);
    edge_scale_kernel<<<(N_EDGES + 255) / 256, 256>>>(edge, prods, att);
}

// round 16
// speedup vs baseline: 1.4012x; 1.4012x over previous
#include <cuda_runtime.h>
#include <cuda_bf16.h>
#include <cstdint>

#define N_NODES 50000
#define N_EDGES 800000
#define D 64
#define DH 8
#define NSEG (N_NODES * DH)

#define TM 128
#define GRID_X ((N_NODES + TM - 1) / TM)   // 391

// smem rows: 32 (hi,lo) uint2 pair-slots per row (64 k = 32 pairs), stride 34
#define SA_STRIDE 34
#define SB_STRIDE 34

// pair-slot permutation within each 8-pair (16-k) block: thread t's pairs
// p=t and p=t+4 land in adjacent slots 2t, 2t+1 (one LDS.128 = both + hi/lo).
__device__ __forceinline__ int pslot(int p) {
    return (p & ~7) + ((p & 3) << 1) + ((p >> 2) & 1);
}

typedef unsigned long long u64;

// Device scratch (no cudaMalloc allowed)
__device__ __align__(16) float g_q[N_NODES * D];
__device__ __align__(16) float g_k[N_NODES * D];
__device__ __align__(16) float g_s[NSEG];

// (hi,lo) bf16x2 split pair for two consecutive k values (even in low half)
__device__ __forceinline__ uint2 mkpair(float e, float o) {
    __nv_bfloat16 he = __float2bfloat16(e), ho = __float2bfloat16(o);
    float re = e - __bfloat162float(he);
    float ro = o - __bfloat162float(ho);
    __nv_bfloat16 le = __float2bfloat16(re), lo2 = __float2bfloat16(ro);
    uint32_t hi = (uint32_t)__bfloat16_as_ushort(he) | ((uint32_t)__bfloat16_as_ushort(ho) << 16);
    uint32_t lo = (uint32_t)__bfloat16_as_ushort(le) | ((uint32_t)__bfloat16_as_ushort(lo2) << 16);
    return make_uint2(hi, lo);
}

__device__ __forceinline__ void mma_bf16(float c[4],
                                         uint32_t a0, uint32_t a1, uint32_t a2, uint32_t a3,
                                         uint32_t b0, uint32_t b1) {
    asm volatile(
        "mma.sync.aligned.m16n8k16.row.col.f32.bf16.bf16.f32 "
        "{%0,%1,%2,%3}, {%4,%5,%6,%7}, {%8,%9}, {%0,%1,%2,%3};"
        : "+f"(c[0]), "+f"(c[1]), "+f"(c[2]), "+f"(c[3])
        : "r"(a0), "r"(a1), "r"(a2), "r"(a3), "r"(b0), "r"(b1));
}

// ---------------------------------------------------------------------------
// Tensor-core QKV GEMM via mma.sync m16n8k16 bf16 (2-term split, fp32 accum).
// Grid (391, 3); 128 threads; warp tile 32x64 (B fragments reused over 2 m).
// m16n8k16 fragment map:
//   A: a0=(g, k=2t,2t+1) a1=(g+8, same) a2=(g, k=2t+8..9) a3=(g+8, same)
//   B: b0=(n=g, k=2t,2t+1) b1=(n=g, k=2t+8..9)   [k-pairs packed, even low]
//   C: c0,c1=(g,2t),(g,2t+1)  c2,c3=(g+8,2t),(g+8,2t+1)
// ---------------------------------------------------------------------------
__global__ __launch_bounds__(128, 4) void qkv_mma_kernel(
    const float* __restrict__ x,
    const float* __restrict__ Wq, const float* __restrict__ bq,
    const float* __restrict__ Wk, const float* __restrict__ bk,
    const float* __restrict__ Wv, const float* __restrict__ bv,
    float* __restrict__ vout)
{
    __shared__ __align__(16) uint2 sA[128 * SA_STRIDE];  // row * 34 + pslot(p)
    __shared__ __align__(16) uint2 sB[64 * SB_STRIDE];   // n   * 34 + pslot(p)

    const int tid = threadIdx.x;
    const int mat = blockIdx.y;
    const int n0 = blockIdx.x * TM;

    const float* W    = (mat == 0) ? Wq : (mat == 1) ? Wk : Wv;
    const float* bias = (mat == 0) ? bq : (mat == 1) ? bk : bv;
    float* dst        = (mat == 0) ? g_q : (mat == 1) ? g_k : vout;

    // Fused init: zero g_s (100000 float4; 391*128 = 50048 thr -> 2 each)
    if (mat == 0) {
        int g = blockIdx.x * 128 + tid;
        if (g < NSEG / 4) ((float4*)g_s)[g] = make_float4(0.f, 0.f, 0.f, 0.f);
        g += GRID_X * 128;
        if (g < NSEG / 4) ((float4*)g_s)[g] = make_float4(0.f, 0.f, 0.f, 0.f);
    }

    // x tile: 128 rows x 64 cols -> bf16 split pairs
    {
        const float4* x4 = (const float4*)x;
#pragma unroll
        for (int i = tid; i < 2048; i += 128) {
            int row = i >> 4;
            int q4  = i & 15;
            int gn  = n0 + row;
            float4 v = (gn < N_NODES) ? x4[(size_t)gn * 16 + q4]
                                      : make_float4(0.f, 0.f, 0.f, 0.f);
            uint2* a = &sA[row * SA_STRIDE];
            a[pslot(q4 * 2)]     = mkpair(v.x, v.y);
            a[pslot(q4 * 2 + 1)] = mkpair(v.z, v.w);
        }
    }
    // W: [k][n] row-major -> sB[n][pslot(k/2)] (transposed; coalesced over n)
    {
#pragma unroll
        for (int i = tid; i < 2048; i += 128) {
            int p = i >> 6;        // k-pair index
            int n = i & 63;
            float e = W[(2 * p) * 64 + n];
            float o = W[(2 * p + 1) * 64 + n];
            sB[n * SB_STRIDE + pslot(p)] = mkpair(e, o);
        }
    }
    __syncthreads();

    const int wid  = tid >> 5;
    const int lane = tid & 31;
    const int g    = lane >> 2;
    const int t    = lane & 3;
    const int mrow = wid * 32;       // warp's 32-row slab (2 m-subtiles)

    float acc0[8][4], acc1[8][4];
#pragma unroll
    for (int n = 0; n < 8; n++)
#pragma unroll
        for (int j = 0; j < 4; j++) { acc0[n][j] = 0.f; acc1[n][j] = 0.f; }

#pragma unroll
    for (int kk = 0; kk < 4; kk++) {
        const int ks = kk * 8 + 2 * t;   // slots 2t,2t+1 = pairs p=t, p=t+4
        // m-subtile 0: rows mrow+g, mrow+g+8
        uint4 A0 = *(const uint4*)&sA[(mrow + g) * SA_STRIDE + ks];
        uint4 A1 = *(const uint4*)&sA[(mrow + g + 8) * SA_STRIDE + ks];
        // m-subtile 1: rows mrow+16+g, mrow+16+g+8
        uint4 A2 = *(const uint4*)&sA[(mrow + 16 + g) * SA_STRIDE + ks];
        uint4 A3 = *(const uint4*)&sA[(mrow + 24 + g) * SA_STRIDE + ks];
#pragma unroll
        for (int n = 0; n < 8; n++) {
            uint4 Bv = *(const uint4*)&sB[(n * 8 + g) * SB_STRIDE + ks];
            uint32_t bh0 = Bv.x, bl0 = Bv.y, bh1 = Bv.z, bl1 = Bv.w;
            mma_bf16(acc0[n], A0.x, A1.x, A0.z, A1.z, bh0, bh1);
            mma_bf16(acc0[n], A0.x, A1.x, A0.z, A1.z, bl0, bl1);
            mma_bf16(acc0[n], A0.y, A1.y, A0.w, A1.w, bh0, bh1);
            mma_bf16(acc1[n], A2.x, A3.x, A2.z, A3.z, bh0, bh1);
            mma_bf16(acc1[n], A2.x, A3.x, A2.z, A3.z, bl0, bl1);
            mma_bf16(acc1[n], A2.y, A3.y, A2.w, A3.w, bh0, bh1);
        }
    }

    // Epilogue (layout validated in R15): rows {g,g+8}, cols {2t,2t+1}
    const int rA = n0 + mrow + g;
    const int rB = rA + 8;
    const int rC = rA + 16;
    const int rD = rA + 24;
#pragma unroll
    for (int n = 0; n < 8; n++) {
        int col = n * 8 + t * 2;
        float2 b2 = *(const float2*)&bias[col];
        if (rA < N_NODES)
            *(float2*)&dst[(size_t)rA * 64 + col] =
                make_float2(acc0[n][0] + b2.x, acc0[n][1] + b2.y);
        if (rB < N_NODES)
            *(float2*)&dst[(size_t)rB * 64 + col] =
                make_float2(acc0[n][2] + b2.x, acc0[n][3] + b2.y);
        if (rC < N_NODES)
            *(float2*)&dst[(size_t)rC * 64 + col] =
                make_float2(acc1[n][0] + b2.x, acc1[n][1] + b2.y);
        if (rD < N_NODES)
            *(float2*)&dst[(size_t)rD * 64 + col] =
                make_float2(acc1[n][2] + b2.x, acc1[n][3] + b2.y);
    }
}

// ---------------------------------------------------------------------------
// Warp-cooperative fused edge pass: logits + exp + vec4-atomic segment sum.
// 8 lanes per edge, 4 edges per warp; all gathers coalesced.
// ---------------------------------------------------------------------------
__global__ __launch_bounds__(256) void edge_fused_kernel(
    const int* __restrict__ edge, float* __restrict__ prods)
{
    const int lane = threadIdx.x & 31;
    const int warp = (blockIdx.x * 256 + threadIdx.x) >> 5;
    const int e0   = warp * 4;
    const int sub  = lane >> 3;
    const int d    = lane & 7;
    const int e    = e0 + sub;

    const int src = edge[e];
    const int dst = edge[N_EDGES + e];

    const float4* q4 = (const float4*)(g_q + src * D);
    const float4* k4 = (const float4*)(g_k + dst * D);

    float4 qa = q4[d];
    float4 qb = q4[d + 8];
    float4 ka = k4[d];
    float4 kb = k4[d + 8];

    float w0 = qa.x * ka.x + qb.x * kb.x;
    float w1 = qa.y * ka.y + qb.y * kb.y;
    float w2 = qa.z * ka.z + qb.z * kb.z;
    float w3 = qa.w * ka.w + qb.w * kb.w;

    const unsigned FULL = 0xffffffffu;

    {
        float t0 = (lane & 4) ? w0 : w2;
        float t1 = (lane & 4) ? w1 : w3;
        float u0 = __shfl_xor_sync(FULL, t0, 4);
        float u1 = __shfl_xor_sync(FULL, t1, 4);
        w0 = ((lane & 4) ? w2 : w0) + u0;
        w1 = ((lane & 4) ? w3 : w1) + u1;
    }
    float p;
    {
        float t2 = (lane & 2) ? w0 : w1;
        float u2 = __shfl_xor_sync(FULL, t2, 2);
        p = ((lane & 2) ? w1 : w0) + u2;
    }
    {
        int srcl = (sub << 3) | ((d >> 2) & 1) | ((d & 1) << 1) | ((d & 2) << 1);
        p = __shfl_sync(FULL, p, srcl);
    }

    p *= 0.35355339059327373f;  // 1/sqrt(8)

    size_t off = (size_t)e0 * 8 + lane;
    prods[off] = p;
    float ev = __expf(p);

    float p1 = __shfl_down_sync(FULL, ev, 1);
    float p2 = __shfl_down_sync(FULL, ev, 2);
    float p3 = __shfl_down_sync(FULL, ev, 3);
    if ((lane & 3) == 0) {
        float* srow = g_s + dst * 8 + (lane & 4);
        asm volatile("red.global.add.v4.f32 [%0], {%1, %2, %3, %4};"
                     :: "l"(srow), "f"(ev), "f"(p1), "f"(p2), "f"(p3) : "memory");
    }
}

// ---------------------------------------------------------------------------
// Pass C: att[e][d] = exp(prods[e][d]) / (s[dst][d] + 1e-16).
// ---------------------------------------------------------------------------
__global__ __launch_bounds__(256) void edge_scale_kernel(
    const int* __restrict__ edge, const float* __restrict__ prods,
    float* __restrict__ att)
{
    int e = blockIdx.x * blockDim.x + threadIdx.x;
    if (e >= N_EDGES) return;
    int dst = edge[N_EDGES + e];

    const float4* sr = (const float4*)(g_s + dst * 8);
    float4 s0 = sr[0];
    float4 s1 = sr[1];

    const float4* pr = (const float4*)(prods + (size_t)e * 8);
    float4 p0 = pr[0];
    float4 p1 = pr[1];

    float4 v0, v1;
    v0.x = __fdividef(__expf(p0.x), s0.x + 1e-16f);
    v0.y = __fdividef(__expf(p0.y), s0.y + 1e-16f);
    v0.z = __fdividef(__expf(p0.z), s0.z + 1e-16f);
    v0.w = __fdividef(__expf(p0.w), s0.w + 1e-16f);
    v1.x = __fdividef(__expf(p1.x), s1.x + 1e-16f);
    v1.y = __fdividef(__expf(p1.y), s1.y + 1e-16f);
    v1.z = __fdividef(__expf(p1.z), s1.z + 1e-16f);
    v1.w = __fdividef(__expf(p1.w), s1.w + 1e-16f);

    float4* ar = (float4*)(att + (size_t)e * 8);
    ar[0] = v0;
    ar[1] = v1;
}

// ---------------------------------------------------------------------------
// kernel_launch
// Inputs (metadata order): x, Wq, bq, Wk, bk, Wv, bv, edge
// Output: attention [E,8] | v [N,8,8] | prods [E,8]  (float32)
// ---------------------------------------------------------------------------
extern "C" void kernel_launch(void* const* d_in, const int* in_sizes, int n_in,
                              void* d_out, int out_size) {
    const float* x  = (const float*)d_in[0];
    const float* Wq = (const float*)d_in[1];
    const float* bq = (const float*)d_in[2];
    const float* Wk = (const float*)d_in[3];
    const float* bk = (const float*)d_in[4];
    const float* Wv = (const float*)d_in[5];
    const float* bv = (const float*)d_in[6];
    const int*   edge = (const int*)d_in[7];

    float* out   = (float*)d_out;
    float* att   = out;                          // E*8
    float* vout  = out + (size_t)N_EDGES * 8;    // N*64
    float* prods = vout + (size_t)N_NODES * 64;  // E*8

    dim3 grid(GRID_X, 3);
    qkv_mma_kernel<<<grid, 128>>>(x, Wq, bq, Wk, bk, Wv, bv, vout);
    edge_fused_kernel<<<N_EDGES / 32, 256>>>(edge, prods);
    edge_scale_kernel<<<(N_EDGES + 255) / 256, 256>>>(edge, prods, att);
}